// round 6
// baseline (speedup 1.0000x reference)
#include <cuda_runtime.h>
#include <math.h>

#define T_OBS   64
#define T_UNOBS 32
#define B       4096
#define D       4
#define H       256
#define G3      768   // 3*H

// ---------------- scratch (static device buffers; no allocation) ----------------
__device__ __align__(128) float g_H1[(size_t)T_OBS * B * H];   // stem out (tf32-rounded)
__device__ __align__(128) float g_GX[(size_t)T_OBS * B * G3];  // precomputed obs input gates
__device__ __align__(128) float g_Wc[G3 * H];                  // wi @ W2 folded (tf32-rounded)
__device__ __align__(128) float g_bc[G3];                      // bi + wi @ b2
__device__ __align__(128) float g_Wir[G3 * H];                 // wi tf32-rounded
__device__ __align__(128) float g_Whr[G3 * H];                 // wh tf32-rounded
__device__ __align__(128) float g_hf[2][B * H];                // hidden, fp32 (double buffered)
__device__ __align__(128) float g_ht[2][B * H];                // hidden, tf32-rounded copy

// ---------------- helpers ----------------
__device__ __forceinline__ float tf32r(float f) {
    unsigned u;
    asm("cvt.rna.tf32.f32 %0, %1;" : "=r"(u) : "f"(f));
    return __uint_as_float(u);
}

__device__ __forceinline__ void mma_tf32(float* c, const unsigned* a, const unsigned* b) {
    asm volatile(
        "mma.sync.aligned.m16n8k8.row.col.f32.tf32.tf32.f32 "
        "{%0,%1,%2,%3}, {%4,%5,%6,%7}, {%8,%9}, {%0,%1,%2,%3};"
        : "+f"(c[0]), "+f"(c[1]), "+f"(c[2]), "+f"(c[3])
        : "r"(a[0]), "r"(a[1]), "r"(a[2]), "r"(a[3]), "r"(b[0]), "r"(b[1]));
}

// ---------------- init hidden to zero (both buffers, parity 0) ----------------
__global__ void zero_h_kernel() {
    int idx = blockIdx.x * blockDim.x + threadIdx.x;
    g_hf[0][idx] = 0.f;
    g_ht[0][idx] = 0.f;
}

// ---------------- round wi / wh to tf32 ----------------
__global__ void round_w_kernel(const float* __restrict__ wi, const float* __restrict__ wh) {
    int i = blockIdx.x * blockDim.x + threadIdx.x;
    g_Wir[i] = tf32r(wi[i]);
    g_Whr[i] = tf32r(wh[i]);
}

// ---------------- fold Wc = wi @ W2 (tf32-rounded), bc = bi + wi @ b2 ----------------
__global__ void wc_kernel(const float* __restrict__ wi, const float* __restrict__ w2,
                          const float* __restrict__ b2, const float* __restrict__ bi) {
    int j = blockIdx.x;   // 0..767
    int k = threadIdx.x;  // 0..255
    float acc = 0.f;
    for (int m = 0; m < H; m++)
        acc = fmaf(wi[j * H + m], w2[m * H + k], acc);
    g_Wc[j * H + k] = tf32r(acc);
    if (k == 0) {
        float a = bi[j];
        for (int m = 0; m < H; m++)
            a = fmaf(wi[j * H + m], b2[m], a);
        g_bc[j] = a;
    }
}

// ---------------- stem layer 1: h1 = leaky_relu([x, dt] @ W1^T + b1) (tf32-rounded) ----------------
__global__ void stem_kernel(const float* __restrict__ x_obs, const float* __restrict__ t_obs,
                            const float* __restrict__ w1, const float* __restrict__ b1) {
    int row = blockIdx.x;      // t*B + b
    int j = threadIdx.x;       // 0..255
    __shared__ float xt[8];
    if (j < 4) {
        xt[j] = x_obs[(size_t)row * 4 + j];
    } else if (j == 4) {
        int t = row >> 12;
        xt[4] = (t == 0) ? 0.f : (t_obs[row] - t_obs[row - B]);
    }
    __syncthreads();
    float acc = b1[j];
#pragma unroll
    for (int k = 0; k < 5; k++)
        acc = fmaf(w1[j * 5 + k], xt[k], acc);
    float v = (acc > 0.f) ? acc : 0.01f * acc;
    g_H1[(size_t)row * H + j] = tf32r(v);
}

// ---------------- big GEMM: g_GX = g_H1 @ g_Wc^T + g_bc  (all 64 obs steps at once) ----------------
// M = 262144, N = 768, K = 256.  Tile 128x128x16, grid (6, 2048).
__global__ __launch_bounds__(256, 2) void gemm_gx() {
    __shared__ float As[2][128][20];
    __shared__ float Bs[2][128][20];

    int tid = threadIdx.x, warp = tid >> 5, lane = tid & 31;
    int q = lane >> 2, r = lane & 3;
    int wm = warp & 3, wn = warp >> 2;

    int nbase = blockIdx.x * 128;
    size_t mbase = (size_t)blockIdx.y * 128;

    int rowL = tid >> 2, kqL = tid & 3;
    const float* Ap = g_H1 + (mbase + rowL) * H + kqL * 4;
    const float* Wp = g_Wc + (size_t)(nbase + rowL) * H + kqL * 4;

    float acc[2][8][4] = {};

    float4 ra0 = *(const float4*)(Ap);
    float4 ra1 = *(const float4*)(Ap + (size_t)64 * H);
    float4 rb0 = *(const float4*)(Wp);
    float4 rb1 = *(const float4*)(Wp + (size_t)64 * H);
    *(float4*)&As[0][rowL][kqL * 4]      = ra0;
    *(float4*)&As[0][rowL + 64][kqL * 4] = ra1;
    *(float4*)&Bs[0][rowL][kqL * 4]      = rb0;
    *(float4*)&Bs[0][rowL + 64][kqL * 4] = rb1;
    __syncthreads();

#pragma unroll 1
    for (int kc = 0; kc < 16; kc++) {
        int buf = kc & 1;
        if (kc < 15) {
            int k0 = (kc + 1) * 16;
            ra0 = *(const float4*)(Ap + k0);
            ra1 = *(const float4*)(Ap + (size_t)64 * H + k0);
            rb0 = *(const float4*)(Wp + k0);
            rb1 = *(const float4*)(Wp + (size_t)64 * H + k0);
        }
#pragma unroll
        for (int ks = 0; ks < 2; ks++) {
            int kk = ks * 8;
            unsigned af[2][4], bf[8][2];
#pragma unroll
            for (int mi = 0; mi < 2; mi++) {
                int rm = wm * 32 + mi * 16 + q;
                af[mi][0] = __float_as_uint(As[buf][rm][kk + r]);
                af[mi][1] = __float_as_uint(As[buf][rm + 8][kk + r]);
                af[mi][2] = __float_as_uint(As[buf][rm][kk + r + 4]);
                af[mi][3] = __float_as_uint(As[buf][rm + 8][kk + r + 4]);
            }
#pragma unroll
            for (int ni = 0; ni < 8; ni++) {
                int cn = wn * 64 + ni * 8 + q;
                bf[ni][0] = __float_as_uint(Bs[buf][cn][kk + r]);
                bf[ni][1] = __float_as_uint(Bs[buf][cn][kk + r + 4]);
            }
#pragma unroll
            for (int mi = 0; mi < 2; mi++)
#pragma unroll
                for (int ni = 0; ni < 8; ni++)
                    mma_tf32(acc[mi][ni], af[mi], bf[ni]);
        }
        if (kc < 15) {
            int nb = (kc + 1) & 1;
            *(float4*)&As[nb][rowL][kqL * 4]      = ra0;
            *(float4*)&As[nb][rowL + 64][kqL * 4] = ra1;
            *(float4*)&Bs[nb][rowL][kqL * 4]      = rb0;
            *(float4*)&Bs[nb][rowL + 64][kqL * 4] = rb1;
            __syncthreads();
        }
    }

#pragma unroll
    for (int mi = 0; mi < 2; mi++) {
        size_t row = mbase + wm * 32 + mi * 16 + q;
#pragma unroll
        for (int ni = 0; ni < 8; ni++) {
            int cl = wn * 64 + ni * 8 + 2 * r;
            float b0 = g_bc[nbase + cl];
            float b1 = g_bc[nbase + cl + 1];
            float2 v0 = {acc[mi][ni][0] + b0, acc[mi][ni][1] + b1};
            float2 v1 = {acc[mi][ni][2] + b0, acc[mi][ni][3] + b1};
            *(float2*)&g_GX[row * G3 + nbase + cl]       = v0;
            *(float2*)&g_GX[(row + 8) * G3 + nbase + cl] = v1;
        }
    }
}

// ---------------- fused step kernel: gate GEMM + GRU update in one launch ----------------
// obs (AR=false): ROWS=64, CHUNKS=3  -> gh = h @ wh^T (3 gate chunks), gx read from g_GX
// ar  (AR=true):  ROWS=32, CHUNKS=6  -> chunks 0-2: gx = h @ wi^T, chunks 3-5: gh = h @ wh^T
// grid: (2 unit-halves, B/ROWS row-blocks), 256 threads.
template<int ROWS, int CHUNKS, bool AR>
__global__ __launch_bounds__(256, 1) void step_fused(
    int obs_t, const float* __restrict__ bi, const float* __restrict__ bh,
    float* __restrict__ zs_out, int oldp) {
    constexpr int COLS = CHUNKS * 128;
    constexpr int MS = ROWS / 16;       // m16 subtiles per warp (warps span all rows)
    constexpr int NS = COLS / 64;       // n8 subtiles per warp (8 warps split n)
    constexpr int SP = COLS + 4;        // gate-staging row stride

    extern __shared__ float sm[];
    float* As = sm;                     // [2][ROWS][20]
    float* Bs = sm + 2 * ROWS * 20;     // [2][COLS][20]
    float* S  = sm;                     // [ROWS][SP]  (aliased; used after K loop)

    int tid = threadIdx.x, warp = tid >> 5, lane = tid & 31;
    int q = lane >> 2, r = lane & 3;
    int wnb = warp * (COLS / 8);        // warp n base
    int u = blockIdx.x * 128;           // unit half base
    int mbase = blockIdx.y * ROWS;

    const float* hA = g_ht[oldp];

    const float* wptr[CHUNKS];
#pragma unroll
    for (int c = 0; c < CHUNKS; c++) {
        if (AR && c < 3) wptr[c] = g_Wir + (size_t)(c * 256 + u) * H;
        else {
            int g = AR ? c - 3 : c;
            wptr[c] = g_Whr + (size_t)(g * 256 + u) * H;
        }
    }

    int rL = tid >> 2, kqL = tid & 3;
    bool aact = (ROWS == 64) || (tid < 128);
    const float* Ap = hA + (size_t)(mbase + rL) * H + kqL * 4;

    float acc[MS][NS][4] = {};

    // ---- prologue: stage 0 ----
    float4 pa;
    float4 pb[NS];
    if (aact) pa = *(const float4*)(Ap);
#pragma unroll
    for (int i = 0; i < NS; i++) {
        int within = (i & 1) * 64 + rL;
        pb[i] = *(const float4*)(wptr[i >> 1] + (size_t)within * H + kqL * 4);
    }
    if (aact) *(float4*)&As[(0 * ROWS + rL) * 20 + kqL * 4] = pa;
#pragma unroll
    for (int i = 0; i < NS; i++)
        *(float4*)&Bs[(0 * COLS + i * 64 + rL) * 20 + kqL * 4] = pb[i];
    __syncthreads();

#pragma unroll 1
    for (int kc = 0; kc < 16; kc++) {
        int buf = kc & 1;
        if (kc < 15) {
            int k0 = (kc + 1) * 16;
            if (aact) pa = *(const float4*)(Ap + k0);
#pragma unroll
            for (int i = 0; i < NS; i++) {
                int within = (i & 1) * 64 + rL;
                pb[i] = *(const float4*)(wptr[i >> 1] + (size_t)within * H + k0 + kqL * 4);
            }
        }
        const float* Ab = &As[(size_t)buf * ROWS * 20];
        const float* Bb = &Bs[(size_t)buf * COLS * 20];
#pragma unroll
        for (int ks = 0; ks < 2; ks++) {
            int kk = ks * 8;
            unsigned af[MS][4], bf[NS][2];
#pragma unroll
            for (int mi = 0; mi < MS; mi++) {
                int rm = mi * 16 + q;
                af[mi][0] = __float_as_uint(Ab[rm * 20 + kk + r]);
                af[mi][1] = __float_as_uint(Ab[(rm + 8) * 20 + kk + r]);
                af[mi][2] = __float_as_uint(Ab[rm * 20 + kk + r + 4]);
                af[mi][3] = __float_as_uint(Ab[(rm + 8) * 20 + kk + r + 4]);
            }
#pragma unroll
            for (int ni = 0; ni < NS; ni++) {
                int cn = wnb + ni * 8 + q;
                bf[ni][0] = __float_as_uint(Bb[cn * 20 + kk + r]);
                bf[ni][1] = __float_as_uint(Bb[cn * 20 + kk + r + 4]);
            }
#pragma unroll
            for (int mi = 0; mi < MS; mi++)
#pragma unroll
                for (int ni = 0; ni < NS; ni++)
                    mma_tf32(acc[mi][ni], af[mi], bf[ni]);
        }
        if (kc < 15) {
            int nb = (kc + 1) & 1;
            if (aact) *(float4*)&As[(nb * ROWS + rL) * 20 + kqL * 4] = pa;
#pragma unroll
            for (int i = 0; i < NS; i++)
                *(float4*)&Bs[(nb * COLS + i * 64 + rL) * 20 + kqL * 4] = pb[i];
            __syncthreads();
        }
    }

    // ---- stage gates into SMEM (reuse As/Bs space) ----
    __syncthreads();
#pragma unroll
    for (int mi = 0; mi < MS; mi++) {
        int r0 = mi * 16 + q;
#pragma unroll
        for (int ni = 0; ni < NS; ni++) {
            int cb = wnb + ni * 8 + 2 * r;
            *(float2*)&S[r0 * SP + cb]       = make_float2(acc[mi][ni][0], acc[mi][ni][1]);
            *(float2*)&S[(r0 + 8) * SP + cb] = make_float2(acc[mi][ni][2], acc[mi][ni][3]);
        }
    }
    __syncthreads();

    // ---- GRU update ----
    int newp = oldp ^ 1;
    float* hfn = g_hf[newp];
    float* htn = g_ht[newp];
    const float* hfo = g_hf[oldp];
    for (int it = tid; it < ROWS * 128; it += 256) {
        int row = it >> 7, uw = it & 127;
        int grow = mbase + row;
        int gu = u + uw;
        float gxr, gxz, gxn, ghr, ghz, ghn;
        if (AR) {
            gxr = S[row * SP + uw]        + bi[gu];
            gxz = S[row * SP + 128 + uw]  + bi[256 + gu];
            gxn = S[row * SP + 256 + uw]  + bi[512 + gu];
            ghr = S[row * SP + 384 + uw]  + bh[gu];
            ghz = S[row * SP + 512 + uw]  + bh[256 + gu];
            ghn = S[row * SP + 640 + uw]  + bh[512 + gu];
        } else {
            const float* gxp = g_GX + ((size_t)obs_t * B + grow) * G3;
            gxr = gxp[gu]; gxz = gxp[256 + gu]; gxn = gxp[512 + gu];
            ghr = S[row * SP + uw]       + bh[gu];
            ghz = S[row * SP + 128 + uw] + bh[256 + gu];
            ghn = S[row * SP + 256 + uw] + bh[512 + gu];
        }
        float rr = 1.f / (1.f + expf(-(gxr + ghr)));
        float ug = 1.f / (1.f + expf(-(gxz + ghz)));
        float nn = tanhf(gxn + rr * ghn);
        size_t idx = (size_t)grow * H + gu;
        float hp = hfo[idx];
        float hn = (1.f - ug) * nn + ug * hp;
        hfn[idx] = hn;
        htn[idx] = tf32r(hn);
        if (zs_out) zs_out[idx] = hn;
    }
}

// ---------------- head: x_hats = zs @ head_w^T + head_b ----------------
__global__ void head_kernel(const float* __restrict__ zs, const float* __restrict__ head_w,
                            const float* __restrict__ head_b, float* __restrict__ xh) {
    int row = blockIdx.x * 8 + (threadIdx.x >> 5);
    int lane = threadIdx.x & 31;
    const float* z = zs + (size_t)row * H;
    float acc[4] = {0.f, 0.f, 0.f, 0.f};
    for (int c = lane; c < H; c += 32) {
        float zv = z[c];
#pragma unroll
        for (int d = 0; d < 4; d++)
            acc[d] = fmaf(zv, head_w[d * H + c], acc[d]);
    }
#pragma unroll
    for (int d = 0; d < 4; d++)
        for (int off = 16; off; off >>= 1)
            acc[d] += __shfl_xor_sync(0xFFFFFFFFu, acc[d], off);
    if (lane < 4)
        xh[(size_t)row * 4 + lane] = acc[lane] + head_b[lane];
}

// ---------------- launch ----------------
extern "C" void kernel_launch(void* const* d_in, const int* in_sizes, int n_in,
                              void* d_out, int out_size) {
    const float* x_obs   = (const float*)d_in[0];
    const float* t_obs   = (const float*)d_in[1];
    const float* stem_w1 = (const float*)d_in[3];
    const float* stem_b1 = (const float*)d_in[4];
    const float* stem_w2 = (const float*)d_in[5];
    const float* stem_b2 = (const float*)d_in[6];
    const float* gru_wi  = (const float*)d_in[7];
    const float* gru_wh  = (const float*)d_in[8];
    const float* gru_bi  = (const float*)d_in[9];
    const float* gru_bh  = (const float*)d_in[10];
    const float* head_w  = (const float*)d_in[11];
    const float* head_b  = (const float*)d_in[12];

    float* out    = (float*)d_out;
    float* x_hats = out;                                 // [32,4096,4]
    float* zs     = out + (size_t)T_UNOBS * B * D;       // [32,4096,256]

    // dynamic smem: obs = max(AsBs 71680, S 99328); ar = max(128000, 98816)
    const int SM_OBS = 99328;
    const int SM_AR  = 128000;
    cudaFuncSetAttribute(step_fused<64, 3, false>,
                         cudaFuncAttributeMaxDynamicSharedMemorySize, SM_OBS);
    cudaFuncSetAttribute(step_fused<32, 6, true>,
                         cudaFuncAttributeMaxDynamicSharedMemorySize, SM_AR);

    zero_h_kernel<<<(B * H) / 256, 256>>>();
    round_w_kernel<<<(G3 * H) / 256, 256>>>(gru_wi, gru_wh);
    wc_kernel<<<G3, H>>>(gru_wi, stem_w2, stem_b2, gru_bi);
    stem_kernel<<<T_OBS * B, H>>>(x_obs, t_obs, stem_w1, stem_b1);

    // all 64 obs-step input gates in one saturated GEMM
    gemm_gx<<<dim3(6, 2048), 256>>>();

    int p = 0;
    for (int t = 0; t < T_OBS; t++) {
        step_fused<64, 3, false><<<dim3(2, B / 64), 256, SM_OBS>>>(
            t, gru_bi, gru_bh, (t == T_OBS - 1) ? zs : (float*)nullptr, p);
        p ^= 1;
    }
    for (int s = 1; s < T_UNOBS; s++) {
        step_fused<32, 6, true><<<dim3(2, B / 32), 256, SM_AR>>>(
            -1, gru_bi, gru_bh, zs + (size_t)s * B * H, p);
        p ^= 1;
    }

    head_kernel<<<(T_UNOBS * B) / 8, 256>>>(zs, head_w, head_b, x_hats);
}

// round 7
// speedup vs baseline: 1.4687x; 1.4687x over previous
#include <cuda_runtime.h>
#include <math.h>

#define T_OBS   64
#define T_UNOBS 32
#define B       4096
#define D       4
#define H       256
#define G3      768    // 3*H
#define NSTEP   95     // 64 obs + 31 ar
#define NCTA    296    // 2 CTAs/SM on 148 SMs -> guaranteed co-resident

// ---------------- scratch (static device buffers; no allocation) ----------------
__device__ __align__(128) float g_H1[(size_t)T_OBS * B * H];  // stem out (tf32-rounded)
__device__ __align__(128) float g_Wc[G3 * H];                 // wi @ W2 folded (tf32-rounded)
__device__ __align__(128) float g_bc[G3];                     // bi + wi @ b2
__device__ __align__(128) float g_Wir[G3 * H];                // wi tf32-rounded
__device__ __align__(128) float g_Whr[G3 * H];                // wh tf32-rounded
__device__ __align__(128) float g_hf[2][B * H];               // hidden fp32 (ping-pong)
__device__ __align__(128) float g_ht[2][B * H];               // hidden tf32-rounded
__device__ __align__(128) float g_G[(size_t)B * 2 * G3];      // per-step gates [gx | gh]
__device__ unsigned g_bar;

// ---------------- helpers ----------------
__device__ __forceinline__ float tf32r(float f) {
    unsigned u;
    asm("cvt.rna.tf32.f32 %0, %1;" : "=r"(u) : "f"(f));
    return __uint_as_float(u);
}

__device__ __forceinline__ void mma_tf32(float* c, const unsigned* a, const unsigned* b) {
    asm volatile(
        "mma.sync.aligned.m16n8k8.row.col.f32.tf32.tf32.f32 "
        "{%0,%1,%2,%3}, {%4,%5,%6,%7}, {%8,%9}, {%0,%1,%2,%3};"
        : "+f"(c[0]), "+f"(c[1]), "+f"(c[2]), "+f"(c[3])
        : "r"(a[0]), "r"(a[1]), "r"(a[2]), "r"(a[3]), "r"(b[0]), "r"(b[1]));
}

// global barrier: monotone counter, release on arrive, acquire on spin
__device__ __forceinline__ void gbar(unsigned target) {
    __syncthreads();
    if (threadIdx.x == 0) {
        __threadfence();
        atomicAdd(&g_bar, 1u);
        unsigned v;
        do {
            asm volatile("ld.acquire.gpu.u32 %0, [%1];" : "=r"(v) : "l"(&g_bar));
            if (v < target) __nanosleep(64);
        } while (v < target);
    }
    __syncthreads();
}

// ---------------- init: hidden zero + barrier reset ----------------
__global__ void zero_kernel() {
    int idx = blockIdx.x * blockDim.x + threadIdx.x;
    g_hf[0][idx] = 0.f;
    g_ht[0][idx] = 0.f;
    if (idx == 0) g_bar = 0u;
}

// ---------------- round wi / wh to tf32 ----------------
__global__ void round_w_kernel(const float* __restrict__ wi, const float* __restrict__ wh) {
    int i = blockIdx.x * blockDim.x + threadIdx.x;
    g_Wir[i] = tf32r(wi[i]);
    g_Whr[i] = tf32r(wh[i]);
}

// ---------------- fold Wc = wi @ W2 (tf32-rounded), bc = bi + wi @ b2 ----------------
__global__ void wc_kernel(const float* __restrict__ wi, const float* __restrict__ w2,
                          const float* __restrict__ b2, const float* __restrict__ bi) {
    int j = blockIdx.x;   // 0..767
    int k = threadIdx.x;  // 0..255
    float acc = 0.f;
    for (int m = 0; m < H; m++)
        acc = fmaf(wi[j * H + m], w2[m * H + k], acc);
    g_Wc[j * H + k] = tf32r(acc);
    if (k == 0) {
        float a = bi[j];
        for (int m = 0; m < H; m++)
            a = fmaf(wi[j * H + m], b2[m], a);
        g_bc[j] = a;
    }
}

// ---------------- stem: h1 = tf32(leaky_relu([x, dt] @ W1^T + b1)), 16 rows/block ----------------
__global__ void stem_kernel(const float* __restrict__ x_obs, const float* __restrict__ t_obs,
                            const float* __restrict__ w1, const float* __restrict__ b1) {
    __shared__ float w1s[H * 5];
    __shared__ float b1s[H];
    __shared__ float xts[16][5];
    int tid = threadIdx.x;
    int r0 = blockIdx.x * 16;

    for (int i = tid; i < H * 5; i += 256) w1s[i] = w1[i];
    b1s[tid] = b1[tid];
    if (tid < 16) {
        int row = r0 + tid;
        float4 xv = *(const float4*)(x_obs + (size_t)row * 4);
        xts[tid][0] = xv.x; xts[tid][1] = xv.y; xts[tid][2] = xv.z; xts[tid][3] = xv.w;
        int t = row >> 12;
        xts[tid][4] = (t == 0) ? 0.f : (t_obs[row] - t_obs[row - B]);
    }
    __syncthreads();

    int cq = (tid & 63) * 4;
    int lr0 = tid >> 6;
    float wv[4][5], bb[4];
#pragma unroll
    for (int c = 0; c < 4; c++) {
        bb[c] = b1s[cq + c];
#pragma unroll
        for (int k = 0; k < 5; k++) wv[c][k] = w1s[(cq + c) * 5 + k];
    }
#pragma unroll
    for (int rr = 0; rr < 4; rr++) {
        int lr = lr0 + rr * 4;
        int row = r0 + lr;
        float4 o;
#pragma unroll
        for (int c = 0; c < 4; c++) {
            float acc = bb[c];
#pragma unroll
            for (int k = 0; k < 5; k++)
                acc = fmaf(wv[c][k], xts[lr][k], acc);
            float v = (acc > 0.f) ? acc : 0.01f * acc;
            (&o.x)[c] = tf32r(v);
        }
        *(float4*)(g_H1 + (size_t)row * H + cq) = o;
    }
}

// ---------------- persistent recurrence: all 95 steps, 2 phases each ----------------
__global__ __launch_bounds__(256, 2) void rnn_persistent(
    const float* __restrict__ bi, const float* __restrict__ bh,
    float* __restrict__ zs_base) {
    __shared__ float As[2][128][20];
    __shared__ float Bs[2][128][20];

    int tid = threadIdx.x, warp = tid >> 5, lane = tid & 31;
    int q = lane >> 2, r = lane & 3;
    int wm = warp & 3, wn = warp >> 2;
    int rank = blockIdx.x;
    int rowL = tid >> 2, kqL = tid & 3;

    for (int step = 0; step < NSTEP; step++) {
        int oldp = step & 1;
        bool ar = (step >= T_OBS);
        const float* hA = g_ht[oldp];

        // ---- phase A: gate GEMM tiles -> g_G (no bias; added in phase B) ----
        for (int tile = rank; tile < 384; tile += NCTA) {
            int tn = tile >> 5;        // 0..11  (consecutive ranks share weight tile)
            int tm = tile & 31;        // 0..31
            const float* A;
            const float* W;
            if (tn < 6) {
                A = ar ? hA : (g_H1 + (size_t)step * B * H);
                W = ar ? g_Wir : g_Wc;
            } else {
                A = hA;
                W = g_Whr;
            }
            int wrow = (tn < 6 ? tn : tn - 6) * 128;   // W row base within [0,768)
            int gcol = tn * 128;                       // g_G col base within [0,1536)
            int mbase = tm * 128;
            const float* Ap = A + (size_t)(mbase + rowL) * H + kqL * 4;
            const float* Wp = W + (size_t)(wrow + rowL) * H + kqL * 4;

            float acc[2][8][4] = {};

            __syncthreads();   // smem buffers reused across tiles
            float4 ra0 = *(const float4*)(Ap);
            float4 ra1 = *(const float4*)(Ap + (size_t)64 * H);
            float4 rb0 = *(const float4*)(Wp);
            float4 rb1 = *(const float4*)(Wp + (size_t)64 * H);
            *(float4*)&As[0][rowL][kqL * 4]      = ra0;
            *(float4*)&As[0][rowL + 64][kqL * 4] = ra1;
            *(float4*)&Bs[0][rowL][kqL * 4]      = rb0;
            *(float4*)&Bs[0][rowL + 64][kqL * 4] = rb1;
            __syncthreads();

#pragma unroll 1
            for (int kc = 0; kc < 16; kc++) {
                int buf = kc & 1;
                if (kc < 15) {
                    int k0 = (kc + 1) * 16;
                    ra0 = *(const float4*)(Ap + k0);
                    ra1 = *(const float4*)(Ap + (size_t)64 * H + k0);
                    rb0 = *(const float4*)(Wp + k0);
                    rb1 = *(const float4*)(Wp + (size_t)64 * H + k0);
                }
#pragma unroll
                for (int ks = 0; ks < 2; ks++) {
                    int kk = ks * 8;
                    unsigned af[2][4], bf[8][2];
#pragma unroll
                    for (int mi = 0; mi < 2; mi++) {
                        int rm = wm * 32 + mi * 16 + q;
                        af[mi][0] = __float_as_uint(As[buf][rm][kk + r]);
                        af[mi][1] = __float_as_uint(As[buf][rm + 8][kk + r]);
                        af[mi][2] = __float_as_uint(As[buf][rm][kk + r + 4]);
                        af[mi][3] = __float_as_uint(As[buf][rm + 8][kk + r + 4]);
                    }
#pragma unroll
                    for (int ni = 0; ni < 8; ni++) {
                        int cn = wn * 64 + ni * 8 + q;
                        bf[ni][0] = __float_as_uint(Bs[buf][cn][kk + r]);
                        bf[ni][1] = __float_as_uint(Bs[buf][cn][kk + r + 4]);
                    }
#pragma unroll
                    for (int mi = 0; mi < 2; mi++)
#pragma unroll
                        for (int ni = 0; ni < 8; ni++)
                            mma_tf32(acc[mi][ni], af[mi], bf[ni]);
                }
                if (kc < 15) {
                    int nb = (kc + 1) & 1;
                    *(float4*)&As[nb][rowL][kqL * 4]      = ra0;
                    *(float4*)&As[nb][rowL + 64][kqL * 4] = ra1;
                    *(float4*)&Bs[nb][rowL][kqL * 4]      = rb0;
                    *(float4*)&Bs[nb][rowL + 64][kqL * 4] = rb1;
                    __syncthreads();
                }
            }

#pragma unroll
            for (int mi = 0; mi < 2; mi++) {
                int row = mbase + wm * 32 + mi * 16 + q;
#pragma unroll
                for (int ni = 0; ni < 8; ni++) {
                    int cl = wn * 64 + ni * 8 + 2 * r;
                    *(float2*)&g_G[(size_t)row * (2 * G3) + gcol + cl] =
                        make_float2(acc[mi][ni][0], acc[mi][ni][1]);
                    *(float2*)&g_G[(size_t)(row + 8) * (2 * G3) + gcol + cl] =
                        make_float2(acc[mi][ni][2], acc[mi][ni][3]);
                }
            }
        }

        gbar((unsigned)(2 * step + 1) * NCTA);

        // ---- phase B: GRU elementwise update ----
        const float* bxi = ar ? bi : g_bc;
        float* hfn = g_hf[oldp ^ 1];
        float* htn = g_ht[oldp ^ 1];
        const float* hfo = g_hf[oldp];
        float* zs_out = nullptr;
        if (step == T_OBS - 1)      zs_out = zs_base;
        else if (ar)                zs_out = zs_base + (size_t)(step - (T_OBS - 1)) * B * H;

        for (int i = rank * 256 + tid; i < B * H / 4; i += NCTA * 256) {
            int b = i >> 6;
            int m4 = (i & 63) * 4;
            const float* g = g_G + (size_t)b * (2 * G3);
            float4 rx = *(const float4*)(g + m4);
            float4 zx = *(const float4*)(g + H + m4);
            float4 nx = *(const float4*)(g + 2 * H + m4);
            float4 rh = *(const float4*)(g + G3 + m4);
            float4 zh = *(const float4*)(g + G3 + H + m4);
            float4 nh = *(const float4*)(g + G3 + 2 * H + m4);
            float4 br = *(const float4*)(bxi + m4);
            float4 bz = *(const float4*)(bxi + H + m4);
            float4 bn = *(const float4*)(bxi + 2 * H + m4);
            float4 cr = *(const float4*)(bh + m4);
            float4 cz = *(const float4*)(bh + H + m4);
            float4 cn = *(const float4*)(bh + 2 * H + m4);
            float4 hp = *(const float4*)(hfo + (size_t)b * H + m4);
            float4 hn4, ht4;
#pragma unroll
            for (int c = 0; c < 4; c++) {
                float gxr = (&rx.x)[c] + (&br.x)[c];
                float gxz = (&zx.x)[c] + (&bz.x)[c];
                float gxn = (&nx.x)[c] + (&bn.x)[c];
                float ghr = (&rh.x)[c] + (&cr.x)[c];
                float ghz = (&zh.x)[c] + (&cz.x)[c];
                float ghn = (&nh.x)[c] + (&cn.x)[c];
                float rr = 1.f / (1.f + expf(-(gxr + ghr)));
                float ug = 1.f / (1.f + expf(-(gxz + ghz)));
                float nn = tanhf(gxn + rr * ghn);
                float hv = (1.f - ug) * nn + ug * (&hp.x)[c];
                (&hn4.x)[c] = hv;
                (&ht4.x)[c] = tf32r(hv);
            }
            *(float4*)(hfn + (size_t)b * H + m4) = hn4;
            *(float4*)(htn + (size_t)b * H + m4) = ht4;
            if (zs_out) *(float4*)(zs_out + (size_t)b * H + m4) = hn4;
        }

        gbar((unsigned)(2 * step + 2) * NCTA);
    }
}

// ---------------- head: x_hats = zs @ head_w^T + head_b ----------------
__global__ void head_kernel(const float* __restrict__ zs, const float* __restrict__ head_w,
                            const float* __restrict__ head_b, float* __restrict__ xh) {
    int row = blockIdx.x * 8 + (threadIdx.x >> 5);
    int lane = threadIdx.x & 31;
    const float* z = zs + (size_t)row * H;
    float acc[4] = {0.f, 0.f, 0.f, 0.f};
    for (int c = lane; c < H; c += 32) {
        float zv = z[c];
#pragma unroll
        for (int d = 0; d < 4; d++)
            acc[d] = fmaf(zv, head_w[d * H + c], acc[d]);
    }
#pragma unroll
    for (int d = 0; d < 4; d++)
        for (int off = 16; off; off >>= 1)
            acc[d] += __shfl_xor_sync(0xFFFFFFFFu, acc[d], off);
    if (lane < 4)
        xh[(size_t)row * 4 + lane] = acc[lane] + head_b[lane];
}

// ---------------- launch ----------------
extern "C" void kernel_launch(void* const* d_in, const int* in_sizes, int n_in,
                              void* d_out, int out_size) {
    const float* x_obs   = (const float*)d_in[0];
    const float* t_obs   = (const float*)d_in[1];
    const float* stem_w1 = (const float*)d_in[3];
    const float* stem_b1 = (const float*)d_in[4];
    const float* stem_w2 = (const float*)d_in[5];
    const float* stem_b2 = (const float*)d_in[6];
    const float* gru_wi  = (const float*)d_in[7];
    const float* gru_wh  = (const float*)d_in[8];
    const float* gru_bi  = (const float*)d_in[9];
    const float* gru_bh  = (const float*)d_in[10];
    const float* head_w  = (const float*)d_in[11];
    const float* head_b  = (const float*)d_in[12];

    float* out    = (float*)d_out;
    float* x_hats = out;                                 // [32,4096,4]
    float* zs     = out + (size_t)T_UNOBS * B * D;       // [32,4096,256]

    zero_kernel<<<(B * H) / 256, 256>>>();
    round_w_kernel<<<(G3 * H) / 256, 256>>>(gru_wi, gru_wh);
    wc_kernel<<<G3, H>>>(gru_wi, stem_w2, stem_b2, gru_bi);
    stem_kernel<<<T_OBS * B / 16, 256>>>(x_obs, t_obs, stem_w1, stem_b1);

    rnn_persistent<<<NCTA, 256>>>(gru_bi, gru_bh, zs);

    head_kernel<<<(T_UNOBS * B) / 8, 256>>>(zs, head_w, head_b, x_hats);
}

// round 8
// speedup vs baseline: 1.5332x; 1.0439x over previous
#include <cuda_runtime.h>
#include <math.h>

#define T_OBS   64
#define T_UNOBS 32
#define B       4096
#define D       4
#define H       256
#define G3      768    // 3*H
#define NSTEP   95     // 64 obs + 31 ar
#define NCTA    296    // 2 CTAs/SM on 148 SMs -> guaranteed co-resident
#define SLABS   32     // m-slabs of 128 rows
#define GRUCH   256    // GRU chunks (16 rows each), chunk r belongs to slab r>>3

// ---------------- scratch (static device buffers; no allocation) ----------------
__device__ __align__(128) float g_H1[(size_t)T_OBS * B * H];  // stem out (tf32-rounded)
__device__ __align__(128) float g_Wc[G3 * H];                 // wi @ W2 folded (tf32-rounded)
__device__ __align__(128) float g_bc[G3];                     // bi + wi @ b2
__device__ __align__(128) float g_Wir[G3 * H];                // wi tf32-rounded
__device__ __align__(128) float g_Whr[G3 * H];                // wh tf32-rounded
__device__ __align__(128) float g_hf[2][B * H];               // hidden fp32 (ping-pong)
__device__ __align__(128) float g_ht[2][B * H];               // hidden tf32-rounded
__device__ __align__(128) float g_G[2][(size_t)B * 2 * G3];   // gates, double buffered by step parity
__device__ unsigned g_tileCnt[SLABS];   // per-slab completed tiles (12/step, monotone)
__device__ unsigned g_gruCnt[SLABS];    // per-slab completed GRU chunks (8/step, monotone)

// ---------------- helpers ----------------
__device__ __forceinline__ float tf32r(float f) {
    unsigned u;
    asm("cvt.rna.tf32.f32 %0, %1;" : "=r"(u) : "f"(f));
    return __uint_as_float(u);
}

__device__ __forceinline__ void mma_tf32(float* c, const unsigned* a, const unsigned* b) {
    asm volatile(
        "mma.sync.aligned.m16n8k8.row.col.f32.tf32.tf32.f32 "
        "{%0,%1,%2,%3}, {%4,%5,%6,%7}, {%8,%9}, {%0,%1,%2,%3};"
        : "+f"(c[0]), "+f"(c[1]), "+f"(c[2]), "+f"(c[3])
        : "r"(a[0]), "r"(a[1]), "r"(a[2]), "r"(a[3]), "r"(b[0]), "r"(b[1]));
}

// spin until *p >= tgt (thread 0 polls, block-wide release via syncthreads)
__device__ __forceinline__ void spin_ge(unsigned* p, unsigned tgt) {
    if (threadIdx.x == 0) {
        unsigned v;
        do {
            asm volatile("ld.acquire.gpu.u32 %0, [%1];" : "=r"(v) : "l"(p) : "memory");
            if (v < tgt) __nanosleep(32);
        } while (v < tgt);
    }
    __syncthreads();
}

// signal: all CTA writes -> visible, then bump counter
__device__ __forceinline__ void signal(unsigned* p) {
    __syncthreads();
    if (threadIdx.x == 0) {
        __threadfence();
        atomicAdd(p, 1u);
    }
}

// ---------------- init: hidden zero + counters reset ----------------
__global__ void zero_kernel() {
    int idx = blockIdx.x * blockDim.x + threadIdx.x;
    g_hf[0][idx] = 0.f;
    g_ht[0][idx] = 0.f;
    if (idx < SLABS) { g_tileCnt[idx] = 0u; g_gruCnt[idx] = 0u; }
}

// ---------------- round wi / wh to tf32 ----------------
__global__ void round_w_kernel(const float* __restrict__ wi, const float* __restrict__ wh) {
    int i = blockIdx.x * blockDim.x + threadIdx.x;
    g_Wir[i] = tf32r(wi[i]);
    g_Whr[i] = tf32r(wh[i]);
}

// ---------------- fold Wc = wi @ W2 (tf32-rounded), bc = bi + wi @ b2 ----------------
__global__ void wc_kernel(const float* __restrict__ wi, const float* __restrict__ w2,
                          const float* __restrict__ b2, const float* __restrict__ bi) {
    int j = blockIdx.x;   // 0..767
    int k = threadIdx.x;  // 0..255
    float acc = 0.f;
    for (int m = 0; m < H; m++)
        acc = fmaf(wi[j * H + m], w2[m * H + k], acc);
    g_Wc[j * H + k] = tf32r(acc);
    if (k == 0) {
        float a = bi[j];
        for (int m = 0; m < H; m++)
            a = fmaf(wi[j * H + m], b2[m], a);
        g_bc[j] = a;
    }
}

// ---------------- stem: h1 = tf32(leaky_relu([x, dt] @ W1^T + b1)), 16 rows/block ----------------
__global__ void stem_kernel(const float* __restrict__ x_obs, const float* __restrict__ t_obs,
                            const float* __restrict__ w1, const float* __restrict__ b1) {
    __shared__ float w1s[H * 5];
    __shared__ float b1s[H];
    __shared__ float xts[16][5];
    int tid = threadIdx.x;
    int r0 = blockIdx.x * 16;

    for (int i = tid; i < H * 5; i += 256) w1s[i] = w1[i];
    b1s[tid] = b1[tid];
    if (tid < 16) {
        int row = r0 + tid;
        float4 xv = *(const float4*)(x_obs + (size_t)row * 4);
        xts[tid][0] = xv.x; xts[tid][1] = xv.y; xts[tid][2] = xv.z; xts[tid][3] = xv.w;
        int t = row >> 12;
        xts[tid][4] = (t == 0) ? 0.f : (t_obs[row] - t_obs[row - B]);
    }
    __syncthreads();

    int cq = (tid & 63) * 4;
    int lr0 = tid >> 6;
    float wv[4][5], bb[4];
#pragma unroll
    for (int c = 0; c < 4; c++) {
        bb[c] = b1s[cq + c];
#pragma unroll
        for (int k = 0; k < 5; k++) wv[c][k] = w1s[(cq + c) * 5 + k];
    }
#pragma unroll
    for (int rr = 0; rr < 4; rr++) {
        int lr = lr0 + rr * 4;
        int row = r0 + lr;
        float4 o;
#pragma unroll
        for (int c = 0; c < 4; c++) {
            float acc = bb[c];
#pragma unroll
            for (int k = 0; k < 5; k++)
                acc = fmaf(wv[c][k], xts[lr][k], acc);
            float v = (acc > 0.f) ? acc : 0.01f * acc;
            (&o.x)[c] = tf32r(v);
        }
        *(float4*)(g_H1 + (size_t)row * H + cq) = o;
    }
}

// ---------------- persistent recurrence: dataflow-synchronized, no global barriers ----------------
__global__ __launch_bounds__(256, 2) void rnn_persistent(
    const float* __restrict__ bi, const float* __restrict__ bh,
    float* __restrict__ zs_base) {
    __shared__ float As[2][128][20];
    __shared__ float Bs[2][128][20];

    int tid = threadIdx.x, warp = tid >> 5, lane = tid & 31;
    int q = lane >> 2, r = lane & 3;
    int wm = warp & 3, wn = warp >> 2;
    int rank = blockIdx.x;
    int rowL = tid >> 2, kqL = tid & 3;

    for (int step = 0; step < NSTEP; step++) {
        int par = step & 1;
        bool ar = (step >= T_OBS);
        const float* hA = g_ht[par];
        float* Gw = g_G[par];

        // ---- GEMM tiles (dataflow gated per slab) ----
        for (int tile = rank; tile < 384; tile += NCTA) {
            int tn = tile >> 5;        // 0..11
            int tm = tile & 31;        // 0..31 (slab)
            bool needsH = ar || (tn >= 6);
            // needsH: wait GRU(step-1, slab tm) done (cnt = 8*step).
            // else (obs gx): only g_G buffer reuse vs step-2 -> cnt >= 8*(step-1).
            unsigned tgt = needsH ? 8u * step : (step ? 8u * (step - 1) : 0u);
            if (tgt) spin_ge(&g_gruCnt[tm], tgt);

            const float* A;
            const float* W;
            if (tn < 6) {
                A = ar ? hA : (g_H1 + (size_t)step * B * H);
                W = ar ? g_Wir : g_Wc;
            } else {
                A = hA;
                W = g_Whr;
            }
            int wrow = (tn < 6 ? tn : tn - 6) * 128;
            int gcol = tn * 128;
            int mbase = tm * 128;
            const float* Ap = A + (size_t)(mbase + rowL) * H + kqL * 4;
            const float* Wp = W + (size_t)(wrow + rowL) * H + kqL * 4;

            float acc[2][8][4] = {};

            __syncthreads();   // smem reuse guard
            float4 ra0 = *(const float4*)(Ap);
            float4 ra1 = *(const float4*)(Ap + (size_t)64 * H);
            float4 rb0 = *(const float4*)(Wp);
            float4 rb1 = *(const float4*)(Wp + (size_t)64 * H);
            *(float4*)&As[0][rowL][kqL * 4]      = ra0;
            *(float4*)&As[0][rowL + 64][kqL * 4] = ra1;
            *(float4*)&Bs[0][rowL][kqL * 4]      = rb0;
            *(float4*)&Bs[0][rowL + 64][kqL * 4] = rb1;
            __syncthreads();

#pragma unroll 1
            for (int kc = 0; kc < 16; kc++) {
                int buf = kc & 1;
                if (kc < 15) {
                    int k0 = (kc + 1) * 16;
                    ra0 = *(const float4*)(Ap + k0);
                    ra1 = *(const float4*)(Ap + (size_t)64 * H + k0);
                    rb0 = *(const float4*)(Wp + k0);
                    rb1 = *(const float4*)(Wp + (size_t)64 * H + k0);
                }
#pragma unroll
                for (int ks = 0; ks < 2; ks++) {
                    int kk = ks * 8;
                    unsigned af[2][4], bf[8][2];
#pragma unroll
                    for (int mi = 0; mi < 2; mi++) {
                        int rm = wm * 32 + mi * 16 + q;
                        af[mi][0] = __float_as_uint(As[buf][rm][kk + r]);
                        af[mi][1] = __float_as_uint(As[buf][rm + 8][kk + r]);
                        af[mi][2] = __float_as_uint(As[buf][rm][kk + r + 4]);
                        af[mi][3] = __float_as_uint(As[buf][rm + 8][kk + r + 4]);
                    }
#pragma unroll
                    for (int ni = 0; ni < 8; ni++) {
                        int cn = wn * 64 + ni * 8 + q;
                        bf[ni][0] = __float_as_uint(Bs[buf][cn][kk + r]);
                        bf[ni][1] = __float_as_uint(Bs[buf][cn][kk + r + 4]);
                    }
#pragma unroll
                    for (int mi = 0; mi < 2; mi++)
#pragma unroll
                        for (int ni = 0; ni < 8; ni++)
                            mma_tf32(acc[mi][ni], af[mi], bf[ni]);
                }
                if (kc < 15) {
                    int nb = (kc + 1) & 1;
                    *(float4*)&As[nb][rowL][kqL * 4]      = ra0;
                    *(float4*)&As[nb][rowL + 64][kqL * 4] = ra1;
                    *(float4*)&Bs[nb][rowL][kqL * 4]      = rb0;
                    *(float4*)&Bs[nb][rowL + 64][kqL * 4] = rb1;
                    __syncthreads();
                }
            }

#pragma unroll
            for (int mi = 0; mi < 2; mi++) {
                int row = mbase + wm * 32 + mi * 16 + q;
#pragma unroll
                for (int ni = 0; ni < 8; ni++) {
                    int cl = wn * 64 + ni * 8 + 2 * r;
                    *(float2*)&Gw[(size_t)row * (2 * G3) + gcol + cl] =
                        make_float2(acc[mi][ni][0], acc[mi][ni][1]);
                    *(float2*)&Gw[(size_t)(row + 8) * (2 * G3) + gcol + cl] =
                        make_float2(acc[mi][ni][2], acc[mi][ni][3]);
                }
            }
            signal(&g_tileCnt[tm]);
        }

        // ---- GRU chunk (16 rows), gated on this slab's 12 tiles ----
        if (rank < GRUCH) {
            int slab = rank >> 3;
            spin_ge(&g_tileCnt[slab], 12u * (step + 1));

            const float* bxi = ar ? bi : g_bc;
            float* hfn = g_hf[par ^ 1];
            float* htn = g_ht[par ^ 1];
            const float* hfo = g_hf[par];
            float* zs_out = nullptr;
            if (step == T_OBS - 1)      zs_out = zs_base;
            else if (ar)                zs_out = zs_base + (size_t)(step - (T_OBS - 1)) * B * H;

            int row0 = rank * 16;
            for (int i = tid; i < 16 * 64; i += 256) {
                int b = row0 + (i >> 6);
                int m4 = (i & 63) * 4;
                const float* g = Gw + (size_t)b * (2 * G3);
                float4 rx = *(const float4*)(g + m4);
                float4 zx = *(const float4*)(g + H + m4);
                float4 nx = *(const float4*)(g + 2 * H + m4);
                float4 rh = *(const float4*)(g + G3 + m4);
                float4 zh = *(const float4*)(g + G3 + H + m4);
                float4 nh = *(const float4*)(g + G3 + 2 * H + m4);
                float4 br = *(const float4*)(bxi + m4);
                float4 bz = *(const float4*)(bxi + H + m4);
                float4 bn = *(const float4*)(bxi + 2 * H + m4);
                float4 cr = *(const float4*)(bh + m4);
                float4 cz = *(const float4*)(bh + H + m4);
                float4 cn = *(const float4*)(bh + 2 * H + m4);
                float4 hp = *(const float4*)(hfo + (size_t)b * H + m4);
                float4 hn4, ht4;
#pragma unroll
                for (int c = 0; c < 4; c++) {
                    float gxr = (&rx.x)[c] + (&br.x)[c];
                    float gxz = (&zx.x)[c] + (&bz.x)[c];
                    float gxn = (&nx.x)[c] + (&bn.x)[c];
                    float ghr = (&rh.x)[c] + (&cr.x)[c];
                    float ghz = (&zh.x)[c] + (&cz.x)[c];
                    float ghn = (&nh.x)[c] + (&cn.x)[c];
                    float rr = 1.f / (1.f + expf(-(gxr + ghr)));
                    float ug = 1.f / (1.f + expf(-(gxz + ghz)));
                    float nn = tanhf(gxn + rr * ghn);
                    float hv = (1.f - ug) * nn + ug * (&hp.x)[c];
                    (&hn4.x)[c] = hv;
                    (&ht4.x)[c] = tf32r(hv);
                }
                *(float4*)(hfn + (size_t)b * H + m4) = hn4;
                *(float4*)(htn + (size_t)b * H + m4) = ht4;
                if (zs_out) *(float4*)(zs_out + (size_t)b * H + m4) = hn4;
            }
            signal(&g_gruCnt[slab]);
        }
    }
}

// ---------------- head: x_hats = zs @ head_w^T + head_b ----------------
__global__ void head_kernel(const float* __restrict__ zs, const float* __restrict__ head_w,
                            const float* __restrict__ head_b, float* __restrict__ xh) {
    int row = blockIdx.x * 8 + (threadIdx.x >> 5);
    int lane = threadIdx.x & 31;
    const float* z = zs + (size_t)row * H;
    float acc[4] = {0.f, 0.f, 0.f, 0.f};
    for (int c = lane; c < H; c += 32) {
        float zv = z[c];
#pragma unroll
        for (int d = 0; d < 4; d++)
            acc[d] = fmaf(zv, head_w[d * H + c], acc[d]);
    }
#pragma unroll
    for (int d = 0; d < 4; d++)
        for (int off = 16; off; off >>= 1)
            acc[d] += __shfl_xor_sync(0xFFFFFFFFu, acc[d], off);
    if (lane < 4)
        xh[(size_t)row * 4 + lane] = acc[lane] + head_b[lane];
}

// ---------------- launch ----------------
extern "C" void kernel_launch(void* const* d_in, const int* in_sizes, int n_in,
                              void* d_out, int out_size) {
    const float* x_obs   = (const float*)d_in[0];
    const float* t_obs   = (const float*)d_in[1];
    const float* stem_w1 = (const float*)d_in[3];
    const float* stem_b1 = (const float*)d_in[4];
    const float* stem_w2 = (const float*)d_in[5];
    const float* stem_b2 = (const float*)d_in[6];
    const float* gru_wi  = (const float*)d_in[7];
    const float* gru_wh  = (const float*)d_in[8];
    const float* gru_bi  = (const float*)d_in[9];
    const float* gru_bh  = (const float*)d_in[10];
    const float* head_w  = (const float*)d_in[11];
    const float* head_b  = (const float*)d_in[12];

    float* out    = (float*)d_out;
    float* x_hats = out;                                 // [32,4096,4]
    float* zs     = out + (size_t)T_UNOBS * B * D;       // [32,4096,256]

    zero_kernel<<<(B * H) / 256, 256>>>();
    round_w_kernel<<<(G3 * H) / 256, 256>>>(gru_wi, gru_wh);
    wc_kernel<<<G3, H>>>(gru_wi, stem_w2, stem_b2, gru_bi);
    stem_kernel<<<T_OBS * B / 16, 256>>>(x_obs, t_obs, stem_w1, stem_b1);

    rnn_persistent<<<NCTA, 256>>>(gru_bi, gru_bh, zs);

    head_kernel<<<(T_UNOBS * B) / 8, 256>>>(zs, head_w, head_b, x_hats);
}

// round 9
// speedup vs baseline: 1.5962x; 1.0411x over previous
#include <cuda_runtime.h>
#include <math.h>

#define T_OBS   64
#define T_UNOBS 32
#define B       4096
#define D       4
#define H       256
#define G3      768    // 3*H
#define NSTEP   95     // 64 obs + 31 ar
#define NCTA    296    // 2 CTAs/SM on 148 SMs -> guaranteed co-resident
#define SLABS   32     // m-slabs of 128 rows
#define GRUCH   256    // GRU chunks (16 rows each), chunk r belongs to slab r>>3
#define STAGES  4
#define SROW    20     // smem row stride (16 + 4 pad floats)

// ---------------- scratch (static device buffers; no allocation) ----------------
__device__ __align__(128) float g_H1[(size_t)T_OBS * B * H];  // stem out (tf32-rounded)
__device__ __align__(128) float g_Wc[G3 * H];                 // wi @ W2 folded (tf32-rounded)
__device__ __align__(128) float g_bc[G3];                     // bi + wi @ b2
__device__ __align__(128) float g_Wir[G3 * H];                // wi tf32-rounded
__device__ __align__(128) float g_Whr[G3 * H];                // wh tf32-rounded
__device__ __align__(128) float g_hf[2][B * H];               // hidden fp32 (ping-pong)
__device__ __align__(128) float g_ht[2][B * H];               // hidden tf32-rounded
__device__ __align__(128) float g_G[2][(size_t)B * 2 * G3];   // gates, double buffered by parity
__device__ unsigned g_tileCnt[SLABS];   // per-slab completed tiles (12/step, monotone)
__device__ unsigned g_gruCnt[SLABS];    // per-slab completed GRU chunks (8/step, monotone)

// ---------------- helpers ----------------
__device__ __forceinline__ float tf32r(float f) {
    unsigned u;
    asm("cvt.rna.tf32.f32 %0, %1;" : "=r"(u) : "f"(f));
    return __uint_as_float(u);
}

__device__ __forceinline__ void mma_tf32(float* c, const unsigned* a, const unsigned* b) {
    asm volatile(
        "mma.sync.aligned.m16n8k8.row.col.f32.tf32.tf32.f32 "
        "{%0,%1,%2,%3}, {%4,%5,%6,%7}, {%8,%9}, {%0,%1,%2,%3};"
        : "+f"(c[0]), "+f"(c[1]), "+f"(c[2]), "+f"(c[3])
        : "r"(a[0]), "r"(a[1]), "r"(a[2]), "r"(a[3]), "r"(b[0]), "r"(b[1]));
}

__device__ __forceinline__ void cp16(float* smem, const float* gmem) {
    unsigned s = (unsigned)__cvta_generic_to_shared(smem);
    asm volatile("cp.async.cg.shared.global [%0], [%1], 16;" :: "r"(s), "l"(gmem));
}

// spin until *p >= tgt (thread 0 polls, block-wide release via syncthreads)
__device__ __forceinline__ void spin_ge(unsigned* p, unsigned tgt) {
    if (threadIdx.x == 0) {
        unsigned v;
        do {
            asm volatile("ld.acquire.gpu.u32 %0, [%1];" : "=r"(v) : "l"(p) : "memory");
            if (v < tgt) __nanosleep(32);
        } while (v < tgt);
    }
    __syncthreads();
}

// signal: all CTA writes -> visible, then bump counter
__device__ __forceinline__ void signal(unsigned* p) {
    __syncthreads();
    if (threadIdx.x == 0) {
        __threadfence();
        atomicAdd(p, 1u);
    }
}

// ---------------- init: hidden zero + counters reset ----------------
__global__ void zero_kernel() {
    int idx = blockIdx.x * blockDim.x + threadIdx.x;
    g_hf[0][idx] = 0.f;
    g_ht[0][idx] = 0.f;
    if (idx < SLABS) { g_tileCnt[idx] = 0u; g_gruCnt[idx] = 0u; }
}

// ---------------- round wi / wh to tf32 ----------------
__global__ void round_w_kernel(const float* __restrict__ wi, const float* __restrict__ wh) {
    int i = blockIdx.x * blockDim.x + threadIdx.x;
    g_Wir[i] = tf32r(wi[i]);
    g_Whr[i] = tf32r(wh[i]);
}

// ---------------- fold Wc = wi @ W2 (tf32-rounded), bc = bi + wi @ b2 ----------------
__global__ void wc_kernel(const float* __restrict__ wi, const float* __restrict__ w2,
                          const float* __restrict__ b2, const float* __restrict__ bi) {
    int j = blockIdx.x;   // 0..767
    int k = threadIdx.x;  // 0..255
    float acc = 0.f;
    for (int m = 0; m < H; m++)
        acc = fmaf(wi[j * H + m], w2[m * H + k], acc);
    g_Wc[j * H + k] = tf32r(acc);
    if (k == 0) {
        float a = bi[j];
        for (int m = 0; m < H; m++)
            a = fmaf(wi[j * H + m], b2[m], a);
        g_bc[j] = a;
    }
}

// ---------------- stem: h1 = tf32(leaky_relu([x, dt] @ W1^T + b1)), 16 rows/block ----------------
__global__ void stem_kernel(const float* __restrict__ x_obs, const float* __restrict__ t_obs,
                            const float* __restrict__ w1, const float* __restrict__ b1) {
    __shared__ float w1s[H * 5];
    __shared__ float b1s[H];
    __shared__ float xts[16][5];
    int tid = threadIdx.x;
    int r0 = blockIdx.x * 16;

    for (int i = tid; i < H * 5; i += 256) w1s[i] = w1[i];
    b1s[tid] = b1[tid];
    if (tid < 16) {
        int row = r0 + tid;
        float4 xv = *(const float4*)(x_obs + (size_t)row * 4);
        xts[tid][0] = xv.x; xts[tid][1] = xv.y; xts[tid][2] = xv.z; xts[tid][3] = xv.w;
        int t = row >> 12;
        xts[tid][4] = (t == 0) ? 0.f : (t_obs[row] - t_obs[row - B]);
    }
    __syncthreads();

    int cq = (tid & 63) * 4;
    int lr0 = tid >> 6;
    float wv[4][5], bb[4];
#pragma unroll
    for (int c = 0; c < 4; c++) {
        bb[c] = b1s[cq + c];
#pragma unroll
        for (int k = 0; k < 5; k++) wv[c][k] = w1s[(cq + c) * 5 + k];
    }
#pragma unroll
    for (int rr = 0; rr < 4; rr++) {
        int lr = lr0 + rr * 4;
        int row = r0 + lr;
        float4 o;
#pragma unroll
        for (int c = 0; c < 4; c++) {
            float acc = bb[c];
#pragma unroll
            for (int k = 0; k < 5; k++)
                acc = fmaf(wv[c][k], xts[lr][k], acc);
            float v = (acc > 0.f) ? acc : 0.01f * acc;
            (&o.x)[c] = tf32r(v);
        }
        *(float4*)(g_H1 + (size_t)row * H + cq) = o;
    }
}

// ---------------- persistent recurrence: dataflow sync + cp.async 4-stage GEMM ----------------
__global__ __launch_bounds__(256, 2) void rnn_persistent(
    const float* __restrict__ bi, const float* __restrict__ bh,
    float* __restrict__ zs_base) {
    extern __shared__ float smemf[];
    float (*As)[128 * SROW] = (float (*)[128 * SROW])smemf;                        // [STAGES][128*SROW]
    float (*Bs)[128 * SROW] = (float (*)[128 * SROW])(smemf + STAGES * 128 * SROW);

    int tid = threadIdx.x, warp = tid >> 5, lane = tid & 31;
    int q = lane >> 2, r = lane & 3;
    int wm = warp & 3, wn = warp >> 2;
    int rank = blockIdx.x;
    int rowL = tid >> 2, kqL = tid & 3;

    for (int step = 0; step < NSTEP; step++) {
        int par = step & 1;
        bool ar = (step >= T_OBS);
        const float* hA = g_ht[par];
        float* Gw = g_G[par];

        // ---- GEMM tiles (dataflow gated per slab) ----
        for (int tile = rank; tile < 384; tile += NCTA) {
            int tn = tile >> 5;        // 0..11
            int tm = tile & 31;        // 0..31 (slab)
            bool needsH = ar || (tn >= 6);
            unsigned tgt = needsH ? 8u * step : (step ? 8u * (step - 1) : 0u);
            if (tgt) spin_ge(&g_gruCnt[tm], tgt);

            const float* A;
            const float* W;
            if (tn < 6) {
                A = ar ? hA : (g_H1 + (size_t)step * B * H);
                W = ar ? g_Wir : g_Wc;
            } else {
                A = hA;
                W = g_Whr;
            }
            int wrow = (tn < 6 ? tn : tn - 6) * 128;
            int gcol = tn * 128;
            int mbase = tm * 128;
            const float* Ap = A + (size_t)(mbase + rowL) * H + kqL * 4;
            const float* Wp = W + (size_t)(wrow + rowL) * H + kqL * 4;

            float acc[2][8][4] = {};

            __syncthreads();   // smem reuse guard across tiles

            // prologue: issue stages 0..2
#pragma unroll
            for (int s = 0; s < STAGES - 1; s++) {
                int k0 = s * 16;
                cp16(&As[s][rowL * SROW + kqL * 4],        Ap + k0);
                cp16(&As[s][(rowL + 64) * SROW + kqL * 4], Ap + (size_t)64 * H + k0);
                cp16(&Bs[s][rowL * SROW + kqL * 4],        Wp + k0);
                cp16(&Bs[s][(rowL + 64) * SROW + kqL * 4], Wp + (size_t)64 * H + k0);
                asm volatile("cp.async.commit_group;");
            }

#pragma unroll 1
            for (int kc = 0; kc < 16; kc++) {
                asm volatile("cp.async.wait_group %0;" :: "n"(STAGES - 2));
                __syncthreads();
                int buf = kc & (STAGES - 1);

                // issue loads for stage kc+3 (overwrites stage (kc-1): finished last iter)
                if (kc + STAGES - 1 < 16) {
                    int s = (kc + STAGES - 1) & (STAGES - 1);
                    int k0 = (kc + STAGES - 1) * 16;
                    cp16(&As[s][rowL * SROW + kqL * 4],        Ap + k0);
                    cp16(&As[s][(rowL + 64) * SROW + kqL * 4], Ap + (size_t)64 * H + k0);
                    cp16(&Bs[s][rowL * SROW + kqL * 4],        Wp + k0);
                    cp16(&Bs[s][(rowL + 64) * SROW + kqL * 4], Wp + (size_t)64 * H + k0);
                }
                asm volatile("cp.async.commit_group;");

                const float* Ab = As[buf];
                const float* Bb = Bs[buf];
#pragma unroll
                for (int ks = 0; ks < 2; ks++) {
                    int kk = ks * 8;
                    unsigned af[2][4], bf[8][2];
#pragma unroll
                    for (int mi = 0; mi < 2; mi++) {
                        int rm = wm * 32 + mi * 16 + q;
                        af[mi][0] = __float_as_uint(Ab[rm * SROW + kk + r]);
                        af[mi][1] = __float_as_uint(Ab[(rm + 8) * SROW + kk + r]);
                        af[mi][2] = __float_as_uint(Ab[rm * SROW + kk + r + 4]);
                        af[mi][3] = __float_as_uint(Ab[(rm + 8) * SROW + kk + r + 4]);
                    }
#pragma unroll
                    for (int ni = 0; ni < 8; ni++) {
                        int cn = wn * 64 + ni * 8 + q;
                        bf[ni][0] = __float_as_uint(Bb[cn * SROW + kk + r]);
                        bf[ni][1] = __float_as_uint(Bb[cn * SROW + kk + r + 4]);
                    }
#pragma unroll
                    for (int mi = 0; mi < 2; mi++)
#pragma unroll
                        for (int ni = 0; ni < 8; ni++)
                            mma_tf32(acc[mi][ni], af[mi], bf[ni]);
                }
            }

#pragma unroll
            for (int mi = 0; mi < 2; mi++) {
                int row = mbase + wm * 32 + mi * 16 + q;
#pragma unroll
                for (int ni = 0; ni < 8; ni++) {
                    int cl = wn * 64 + ni * 8 + 2 * r;
                    *(float2*)&Gw[(size_t)row * (2 * G3) + gcol + cl] =
                        make_float2(acc[mi][ni][0], acc[mi][ni][1]);
                    *(float2*)&Gw[(size_t)(row + 8) * (2 * G3) + gcol + cl] =
                        make_float2(acc[mi][ni][2], acc[mi][ni][3]);
                }
            }
            signal(&g_tileCnt[tm]);
        }

        // ---- GRU chunk (16 rows), gated on this slab's 12 tiles ----
        if (rank < GRUCH) {
            int slab = rank >> 3;
            spin_ge(&g_tileCnt[slab], 12u * (step + 1));

            const float* bxi = ar ? bi : g_bc;
            float* hfn = g_hf[par ^ 1];
            float* htn = g_ht[par ^ 1];
            const float* hfo = g_hf[par];
            float* zs_out = nullptr;
            if (step == T_OBS - 1)      zs_out = zs_base;
            else if (ar)                zs_out = zs_base + (size_t)(step - (T_OBS - 1)) * B * H;

            int row0 = rank * 16;
            for (int i = tid; i < 16 * 64; i += 256) {
                int b = row0 + (i >> 6);
                int m4 = (i & 63) * 4;
                const float* g = Gw + (size_t)b * (2 * G3);
                float4 rx = *(const float4*)(g + m4);
                float4 zx = *(const float4*)(g + H + m4);
                float4 nx = *(const float4*)(g + 2 * H + m4);
                float4 rh = *(const float4*)(g + G3 + m4);
                float4 zh = *(const float4*)(g + G3 + H + m4);
                float4 nh = *(const float4*)(g + G3 + 2 * H + m4);
                float4 br = *(const float4*)(bxi + m4);
                float4 bz = *(const float4*)(bxi + H + m4);
                float4 bn = *(const float4*)(bxi + 2 * H + m4);
                float4 cr = *(const float4*)(bh + m4);
                float4 cz = *(const float4*)(bh + H + m4);
                float4 cn = *(const float4*)(bh + 2 * H + m4);
                float4 hp = *(const float4*)(hfo + (size_t)b * H + m4);
                float4 hn4, ht4;
#pragma unroll
                for (int c = 0; c < 4; c++) {
                    float gxr = (&rx.x)[c] + (&br.x)[c];
                    float gxz = (&zx.x)[c] + (&bz.x)[c];
                    float gxn = (&nx.x)[c] + (&bn.x)[c];
                    float ghr = (&rh.x)[c] + (&cr.x)[c];
                    float ghz = (&zh.x)[c] + (&cz.x)[c];
                    float ghn = (&nh.x)[c] + (&cn.x)[c];
                    float rr = 1.f / (1.f + expf(-(gxr + ghr)));
                    float ug = 1.f / (1.f + expf(-(gxz + ghz)));
                    float nn = tanhf(gxn + rr * ghn);
                    float hv = (1.f - ug) * nn + ug * (&hp.x)[c];
                    (&hn4.x)[c] = hv;
                    (&ht4.x)[c] = tf32r(hv);
                }
                *(float4*)(hfn + (size_t)b * H + m4) = hn4;
                *(float4*)(htn + (size_t)b * H + m4) = ht4;
                if (zs_out) *(float4*)(zs_out + (size_t)b * H + m4) = hn4;
            }
            signal(&g_gruCnt[slab]);
        }
    }
}

// ---------------- head: x_hats = zs @ head_w^T + head_b ----------------
__global__ void head_kernel(const float* __restrict__ zs, const float* __restrict__ head_w,
                            const float* __restrict__ head_b, float* __restrict__ xh) {
    int row = blockIdx.x * 8 + (threadIdx.x >> 5);
    int lane = threadIdx.x & 31;
    const float* z = zs + (size_t)row * H;
    float acc[4] = {0.f, 0.f, 0.f, 0.f};
    for (int c = lane; c < H; c += 32) {
        float zv = z[c];
#pragma unroll
        for (int d = 0; d < 4; d++)
            acc[d] = fmaf(zv, head_w[d * H + c], acc[d]);
    }
#pragma unroll
    for (int d = 0; d < 4; d++)
        for (int off = 16; off; off >>= 1)
            acc[d] += __shfl_xor_sync(0xFFFFFFFFu, acc[d], off);
    if (lane < 4)
        xh[(size_t)row * 4 + lane] = acc[lane] + head_b[lane];
}

// ---------------- launch ----------------
extern "C" void kernel_launch(void* const* d_in, const int* in_sizes, int n_in,
                              void* d_out, int out_size) {
    const float* x_obs   = (const float*)d_in[0];
    const float* t_obs   = (const float*)d_in[1];
    const float* stem_w1 = (const float*)d_in[3];
    const float* stem_b1 = (const float*)d_in[4];
    const float* stem_w2 = (const float*)d_in[5];
    const float* stem_b2 = (const float*)d_in[6];
    const float* gru_wi  = (const float*)d_in[7];
    const float* gru_wh  = (const float*)d_in[8];
    const float* gru_bi  = (const float*)d_in[9];
    const float* gru_bh  = (const float*)d_in[10];
    const float* head_w  = (const float*)d_in[11];
    const float* head_b  = (const float*)d_in[12];

    float* out    = (float*)d_out;
    float* x_hats = out;                                 // [32,4096,4]
    float* zs     = out + (size_t)T_UNOBS * B * D;       // [32,4096,256]

    const int SMEM = STAGES * 128 * SROW * 4 * 2;        // 81920 bytes
    cudaFuncSetAttribute(rnn_persistent,
                         cudaFuncAttributeMaxDynamicSharedMemorySize, SMEM);

    zero_kernel<<<(B * H) / 256, 256>>>();
    round_w_kernel<<<(G3 * H) / 256, 256>>>(gru_wi, gru_wh);
    wc_kernel<<<G3, H>>>(gru_wi, stem_w2, stem_b2, gru_bi);
    stem_kernel<<<T_OBS * B / 16, 256>>>(x_obs, t_obs, stem_w1, stem_b1);

    rnn_persistent<<<NCTA, 256, SMEM>>>(gru_bi, gru_bh, zs);

    head_kernel<<<(T_UNOBS * B) / 8, 256>>>(zs, head_w, head_b, x_hats);
}